// round 2
// baseline (speedup 1.0000x reference)
#include <cuda_runtime.h>
#include <math.h>

// ---------------- problem constants ----------------
// B=4 S=3 E=7 IMG=256 PH=8 H=32 D=128 NH=4 DK=64 DC=128 DH=32 TEMB=256 LK=128 GROUPS=16
#define EPSV 1e-5f

// ---------------- scratch buffers (device globals; no allocation) ----------------
__device__ float g_xin [12 * 448 * 1024];   // patchified input (12,448,32,32)
__device__ float g_xg  [4 * 393216];        // conv1 out in xg flat layout (B, 393216)
__device__ float g_gn_mu[64];
__device__ float g_gn_rs[64];
__device__ float g_xq  [4096 * 128];        // S-collapsed normalized features
__device__ float g_q   [4096 * 256];        // query projections
__device__ float g_oflat[4096 * 128];       // attention output, (Nq, DC) flat
__device__ float g_o2  [4 * 128 * 1024];    // outproj output as (4,128,32,32)
__device__ float g_u   [4 * 7 * 65536];     // unpatched image (B,E,256,256) == skip
__device__ float g_mod [4 * 14];
__device__ float g_lnp [4 * 32 * 2];
__device__ float g_ln  [4 * 2];             // per-batch mu, rstd

// ---------------- K1: patchify ----------------
// xin[img][ic][y][x] = x[b][s][e][y*8+ph1][x*8+ph2], ic = ph1*56+ph2*7+e, img=b*3+s
__global__ void k_patchify(const float* __restrict__ x) {
    int idx = blockIdx.x * 256 + threadIdx.x;
    if (idx >= 12 * 448 * 1024) return;
    int p   = idx & 1023;
    int ic  = (idx >> 10) % 448;
    int img = idx / (448 * 1024);
    int y = p >> 5, xx = p & 31;
    int ph1 = ic / 56, r = ic % 56, ph2 = r / 7, e = r % 7;
    int b = img / 3, s = img % 3;
    g_xin[idx] = x[(((b * 3 + s) * 7 + e) * 256 + (y * 8 + ph1)) * 256 + (xx * 8 + ph2)];
}

// ---------------- K2: 3x3 conv, implicit GEMM ----------------
// Tile: 128 px (4 rows x 32 cols) x 32 oc, 256 threads, CK=8 input-channel chunks.
// MODE 0: in=g_xin (IC=448), out=g_xg scrambled layout, adds patch_b + pos_embed
// MODE 1: in=g_o2 (IC=128), out=g_u unpatch layout, adds unpatch_b
template<int IC, int MODE>
__global__ void __launch_bounds__(256) k_conv3x3(const float* __restrict__ w,
                                                 const float* __restrict__ bias,
                                                 const float* __restrict__ pos) {
    const int CK = 8;
    __shared__ float s_in[CK * 6 * 37];     // rows y0-1..y0+4, cols -1..32 (+pad)
    __shared__ float s_w [CK * 9 * 33];     // [rk=c*9+k][oc_local] padded to 33

    const float* in = (MODE == 0) ? g_xin : g_o2;

    int bx  = blockIdx.x;
    int img = bx >> 3, rb = bx & 7;
    int oc0 = blockIdx.y * 32;
    int t   = threadIdx.x;
    int tx  = t & 15, ty = t >> 4;
    int yl  = tx >> 2;              // 0..3 local out row
    int x0  = (tx & 3) * 8;         // 0,8,16,24 local out col base
    int ty2 = ty * 2;
    int y0  = rb * 4;

    float acc[2][8];
#pragma unroll
    for (int j = 0; j < 2; ++j)
#pragma unroll
        for (int i = 0; i < 8; ++i) acc[j][i] = 0.f;

    for (int ch = 0; ch < IC / CK; ++ch) {
        int ic0 = ch * CK;
        __syncthreads();
        // stage input tile (with halo, zero padded)
        for (int idx = t; idx < CK * 6 * 37; idx += 256) {
            int c  = idx / (6 * 37);
            int rr = idx % (6 * 37);
            int ry = rr / 37, cx = rr % 37;
            int y  = y0 - 1 + ry;
            int xg = cx - 1;
            float v = 0.f;
            if (cx < 34 && y >= 0 && y < 32 && xg >= 0 && xg < 32)
                v = in[((img * IC + ic0 + c) * 32 + y) * 32 + xg];
            s_in[idx] = v;
        }
        // stage weights: 32 oc x CK ic x 9 taps
        for (int idx = t; idx < 32 * CK * 9; idx += 256) {
            int ocl = idx / (CK * 9);
            int rk  = idx % (CK * 9);
            s_w[rk * 33 + ocl] = w[(oc0 + ocl) * (IC * 9) + ic0 * 9 + rk];
        }
        __syncthreads();

#pragma unroll 2
        for (int c = 0; c < CK; ++c) {
#pragma unroll
            for (int ky = 0; ky < 3; ++ky) {
                const float* rp = &s_in[(c * 6 + yl + ky) * 37 + x0];
                float rin[10];
#pragma unroll
                for (int m = 0; m < 10; ++m) rin[m] = rp[m];
#pragma unroll
                for (int kx = 0; kx < 3; ++kx) {
                    int wb = (c * 9 + ky * 3 + kx) * 33 + ty2;
                    float w0 = s_w[wb], w1 = s_w[wb + 1];
#pragma unroll
                    for (int i = 0; i < 8; ++i) {
                        float a = rin[kx + i];
                        acc[0][i] = fmaf(w0, a, acc[0][i]);
                        acc[1][i] = fmaf(w1, a, acc[1][i]);
                    }
                }
            }
        }
    }

    // epilogue
#pragma unroll
    for (int j = 0; j < 2; ++j) {
        int oc = oc0 + ty2 + j;
        float bv = bias[oc];
        int y = y0 + yl;
        if (MODE == 0) {
            int b = img / 3, s = img % 3;
#pragma unroll
            for (int i = 0; i < 8; ++i) {
                int p = y * 32 + x0 + i;
                g_xg[b * 393216 + s * 131072 + oc * 1024 + p] =
                    acc[j][i] + bv + pos[oc * 1024 + p];
            }
        } else {
            int ph1 = oc / 56, r = oc % 56, ph2 = r / 7, e = r % 7;
#pragma unroll
            for (int i = 0; i < 8; ++i) {
                int xg = x0 + i;
                g_u[((img * 7 + e) * 256 + y * 8 + ph1) * 256 + (xg * 8 + ph2)] =
                    acc[j][i] + bv;
            }
        }
    }
}

// ---------------- K3: GroupNorm stats (64 contiguous groups of 24576) ----------------
__global__ void k_gnstats() {
    int bg = blockIdx.x;
    const float* p = g_xg + bg * 24576;
    int t = threadIdx.x;
    float s = 0.f, s2 = 0.f;
    for (int i = t; i < 24576; i += 256) { float v = p[i]; s += v; s2 += v * v; }
    __shared__ float rs[256], rq[256];
    rs[t] = s; rq[t] = s2; __syncthreads();
    for (int off = 128; off > 0; off >>= 1) {
        if (t < off) { rs[t] += rs[t + off]; rq[t] += rq[t + off]; }
        __syncthreads();
    }
    if (t == 0) {
        float mu = rs[0] * (1.f / 24576.f);
        float var = rq[0] * (1.f / 24576.f) - mu * mu;
        g_gn_mu[bg] = mu;
        g_gn_rs[bg] = rsqrtf(var + EPSV);
    }
}

// ---------------- K4: S-collapse with GN applied ----------------
// xq[nq][dq] = sum_sq w2[sq] * xn_flat[nq*384 + dq*3 + sq]
__global__ void k_xq(const float* __restrict__ gamma, const float* __restrict__ beta,
                     const float* __restrict__ w2) {
    int idx = blockIdx.x * 256 + threadIdx.x;
    if (idx >= 4096 * 128) return;
    int nq = idx >> 7, dq = idx & 127;
    int b = nq >> 10;
    int fbase = (nq & 1023) * 384 + dq * 3;
    const float* xb = g_xg + b * 393216;
    float accv = 0.f;
#pragma unroll
    for (int sq = 0; sq < 3; ++sq) {
        int f  = fbase + sq;
        int dp = f / 3072;                 // channel for gamma/beta
        int gi = b * 16 + f / 24576;       // group
        float v = xb[f];
        float xn = (v - g_gn_mu[gi]) * g_gn_rs[gi] * gamma[dp] + beta[dp];
        accv = fmaf(w2[sq], xn, accv);
    }
    g_xq[idx] = accv;
}

// ---------------- K5: q GEMM (4096x128 @ 128x256) ----------------
__global__ void __launch_bounds__(256) k_qgemm(const float* __restrict__ w1,
                                               const float* __restrict__ b1,
                                               const float* __restrict__ w2,
                                               const float* __restrict__ b2p) {
    __shared__ float As[64 * 68];
    __shared__ float Bs[64 * 68];
    int r0 = blockIdx.x * 64, o0 = blockIdx.y * 64;
    int t = threadIdx.x;
    int cth = (t & 15) * 4, rth = (t >> 4) * 4;
    float acc[4][4];
#pragma unroll
    for (int a = 0; a < 4; ++a)
#pragma unroll
        for (int c = 0; c < 4; ++c) acc[a][c] = 0.f;

    for (int k0 = 0; k0 < 128; k0 += 64) {
        __syncthreads();
        for (int idx = t; idx < 4096; idx += 256) {
            int jj = idx & 63, rr = idx >> 6;
            As[jj * 68 + rr] = g_xq[(r0 + rr) * 128 + k0 + jj];
            Bs[jj * 68 + rr] = w1[(o0 + rr) * 128 + k0 + jj];
        }
        __syncthreads();
#pragma unroll 8
        for (int j = 0; j < 64; ++j) {
            float4 av = *(const float4*)&As[j * 68 + rth];
            float4 bv = *(const float4*)&Bs[j * 68 + cth];
            float a[4] = {av.x, av.y, av.z, av.w};
            float bb[4] = {bv.x, bv.y, bv.z, bv.w};
#pragma unroll
            for (int r = 0; r < 4; ++r)
#pragma unroll
                for (int c = 0; c < 4; ++c) acc[r][c] = fmaf(a[r], bb[c], acc[r][c]);
        }
    }
    float w2s = w2[0] + w2[1] + w2[2];
    float b2v = b2p[0];
#pragma unroll
    for (int r = 0; r < 4; ++r)
#pragma unroll
        for (int c = 0; c < 4; ++c) {
            int o = o0 + cth + c;
            g_q[(r0 + rth + r) * 256 + o] = acc[r][c] + b1[o] * w2s + b2v;
        }
}

// ---------------- K6: per-row attention (16384 rows) ----------------
__global__ void __launch_bounds__(128) k_attn(const float* __restrict__ kc,
                                              const float* __restrict__ vc) {
    int n = blockIdx.x;
    int t = threadIdx.x;
    int lane = t & 31, wid = t >> 5;
    __shared__ float attn_s[128];
    __shared__ float red[128];

    const float* qp = g_q + (size_t)(n >> 2) * 256 + (n & 3) * 64;
    float2 q2 = *(const float2*)(qp + 2 * lane);
    const float* kb = kc + (size_t)n * 8192;

#pragma unroll 4
    for (int i = 0; i < 32; ++i) {
        int l = wid * 32 + i;
        float2 kv = *(const float2*)(kb + l * 64 + 2 * lane);
        float p = q2.x * kv.x + q2.y * kv.y;
        p += __shfl_xor_sync(0xffffffffu, p, 16);
        p += __shfl_xor_sync(0xffffffffu, p, 8);
        p += __shfl_xor_sync(0xffffffffu, p, 4);
        p += __shfl_xor_sync(0xffffffffu, p, 2);
        p += __shfl_xor_sync(0xffffffffu, p, 1);
        if (lane == i) attn_s[l] = p * 0.125f;   // 1/sqrt(64)
    }
    __syncthreads();

    float v = attn_s[t];
    float m = v;
    m = fmaxf(m, __shfl_xor_sync(0xffffffffu, m, 16));
    m = fmaxf(m, __shfl_xor_sync(0xffffffffu, m, 8));
    m = fmaxf(m, __shfl_xor_sync(0xffffffffu, m, 4));
    m = fmaxf(m, __shfl_xor_sync(0xffffffffu, m, 2));
    m = fmaxf(m, __shfl_xor_sync(0xffffffffu, m, 1));
    if (lane == 0) red[wid] = m;
    __syncthreads();
    float bm = fmaxf(fmaxf(red[0], red[1]), fmaxf(red[2], red[3]));
    float e = expf(v - bm);
    float s = e;
    s += __shfl_xor_sync(0xffffffffu, s, 16);
    s += __shfl_xor_sync(0xffffffffu, s, 8);
    s += __shfl_xor_sync(0xffffffffu, s, 4);
    s += __shfl_xor_sync(0xffffffffu, s, 2);
    s += __shfl_xor_sync(0xffffffffu, s, 1);
    __syncthreads();
    if (lane == 0) red[wid] = s;
    __syncthreads();
    float bs = red[0] + red[1] + red[2] + red[3];
    attn_s[t] = e * (1.f / bs);
    __syncthreads();

    int c = t & 31, chunk = t >> 5;
    const float* vb = vc + (size_t)n * 4096;
    float acc = 0.f;
#pragma unroll 8
    for (int i = 0; i < 32; ++i) {
        int l = chunk * 32 + i;
        acc = fmaf(attn_s[l], vb[l * 32 + c], acc);
    }
    __syncthreads();
    red[t] = acc;
    __syncthreads();
    if (t < 32) {
        float o = red[t] + red[32 + t] + red[64 + t] + red[96 + t];
        // o.reshape(NH,Nq,DH).transpose(1,0,2): row n -> (h=n/4096, nq=n%4096)
        g_oflat[(n & 4095) * 128 + (n >> 12) * 32 + t] = o;
    }
}

// ---------------- K7: outproj 128x128 per-pixel matvec ----------------
__global__ void __launch_bounds__(256) k_outproj(const float* __restrict__ w,
                                                 const float* __restrict__ bias) {
    __shared__ float in_s[32 * 128];
    __shared__ float w_s[32 * 36];
    int b = blockIdx.x >> 3, pt = blockIdx.x & 7;
    int oc0 = blockIdx.y * 32;
    int t = threadIdx.x;
    int tx = t & 15, ty = t >> 4;
    int p0 = tx * 8, ol = ty * 2;
    float acc[2][8];
#pragma unroll
    for (int j = 0; j < 2; ++j)
#pragma unroll
        for (int i = 0; i < 8; ++i) acc[j][i] = 0.f;

    for (int c0 = 0; c0 < 128; c0 += 32) {
        __syncthreads();
        for (int idx = t; idx < 32 * 128; idx += 256) {
            int c = idx >> 7, p = idx & 127;
            in_s[idx] = g_oflat[b * 131072 + (c0 + c) * 1024 + pt * 128 + p];
        }
        for (int idx = t; idx < 32 * 32; idx += 256) {
            int c = idx & 31, o = idx >> 5;
            w_s[c * 36 + o] = w[(oc0 + o) * 128 + c0 + c];
        }
        __syncthreads();
#pragma unroll 4
        for (int c = 0; c < 32; ++c) {
            float w0 = w_s[c * 36 + ol], w1 = w_s[c * 36 + ol + 1];
            float4 i0 = *(const float4*)&in_s[c * 128 + p0];
            float4 i1 = *(const float4*)&in_s[c * 128 + p0 + 4];
            float iv[8] = {i0.x, i0.y, i0.z, i0.w, i1.x, i1.y, i1.z, i1.w};
#pragma unroll
            for (int i = 0; i < 8; ++i) {
                acc[0][i] = fmaf(w0, iv[i], acc[0][i]);
                acc[1][i] = fmaf(w1, iv[i], acc[1][i]);
            }
        }
    }
#pragma unroll
    for (int j = 0; j < 2; ++j) {
        int oc = oc0 + ol + j;
        float bv = bias[oc];
#pragma unroll
        for (int i = 0; i < 8; ++i)
            g_o2[(b * 128 + oc) * 1024 + pt * 128 + p0 + i] = acc[j][i] + bv;
    }
}

// ---------------- K9: modulation c = silu(emb) @ mod_w.T + mod_b ----------------
__global__ void k_mod(const float* __restrict__ emb, const float* __restrict__ mw,
                      const float* __restrict__ mb) {
    int t = threadIdx.x;
    if (t < 56) {
        int b = t / 14, o = t % 14;
        float accv = mb[o];
        for (int k = 0; k < 256; ++k) {
            float e = emb[b * 256 + k];
            float si = e / (1.f + expf(-e));
            accv = fmaf(si, mw[o * 256 + k], accv);
        }
        g_mod[t] = accv;
    }
}

// ---------------- K10/K11: LayerNorm over u per batch ----------------
__global__ void k_lnpart() {
    int bidx = blockIdx.x;
    int b = bidx >> 5, part = bidx & 31;
    const float* p = g_u + b * 458752 + part * 14336;
    int t = threadIdx.x;
    float s = 0.f, s2 = 0.f;
    for (int i = t; i < 14336; i += 256) { float v = p[i]; s += v; s2 += v * v; }
    __shared__ float rs[256], rq[256];
    rs[t] = s; rq[t] = s2; __syncthreads();
    for (int off = 128; off > 0; off >>= 1) {
        if (t < off) { rs[t] += rs[t + off]; rq[t] += rq[t + off]; }
        __syncthreads();
    }
    if (t == 0) { g_lnp[bidx * 2] = rs[0]; g_lnp[bidx * 2 + 1] = rq[0]; }
}

__global__ void k_lnfin() {
    int t = threadIdx.x;
    if (t < 4) {
        float s = 0.f, s2 = 0.f;
        for (int i = 0; i < 32; ++i) {
            s  += g_lnp[(t * 32 + i) * 2];
            s2 += g_lnp[(t * 32 + i) * 2 + 1];
        }
        float mu = s * (1.f / 458752.f);
        float var = s2 * (1.f / 458752.f) - mu * mu;
        g_ln[t * 2] = mu;
        g_ln[t * 2 + 1] = rsqrtf(var + EPSV);
    }
}

// ---------------- K12: final elementwise tail ----------------
__device__ __forceinline__ float gelu_exact(float x) {
    return 0.5f * x * (1.f + erff(x * 0.70710678118654752f));
}

__global__ void k_final(const float* __restrict__ ew, const float* __restrict__ eb,
                        const float* __restrict__ fw, const float* __restrict__ fb,
                        float* __restrict__ out) {
    int gid = blockIdx.x * 256 + threadIdx.x;
    if (gid >= 262144) return;
    int b = gid >> 16, p = gid & 65535;
    float mu = g_ln[b * 2], rsd = g_ln[b * 2 + 1];
    float uv[7], un[7];
#pragma unroll
    for (int e = 0; e < 7; ++e) {
        uv[e] = g_u[b * 458752 + e * 65536 + p];
        float sc = g_mod[b * 14 + e];
        float sh = g_mod[b * 14 + 7 + e];
        un[e] = (uv[e] - mu) * rsd * (1.f + sc) + sh;
    }
    float en[14];
#pragma unroll
    for (int o = 0; o < 14; ++o) {
        float a = eb[o];
#pragma unroll
        for (int e = 0; e < 7; ++e) a = fmaf(ew[o * 7 + e], un[e], a);
        en[o] = a;
    }
    float hf[7];
#pragma unroll
    for (int e = 0; e < 7; ++e)
        hf[e] = gelu_exact(un[e]) + en[e] * gelu_exact(en[7 + e]);
#pragma unroll
    for (int o = 0; o < 7; ++o) {
        float a = fb[o];
#pragma unroll
        for (int e = 0; e < 7; ++e) a = fmaf(fw[o * 7 + e], hf[e], a);
        out[b * 458752 + o * 65536 + p] = a + uv[o];
    }
}

// ---------------- launch ----------------
extern "C" void kernel_launch(void* const* d_in, const int* in_sizes, int n_in,
                              void* d_out, int out_size) {
    const float* x    = (const float*)d_in[0];
    const float* kc   = (const float*)d_in[1];
    const float* vc   = (const float*)d_in[2];
    const float* emb  = (const float*)d_in[3];
    const float* pos  = (const float*)d_in[4];
    const float* pw   = (const float*)d_in[5];
    const float* pb   = (const float*)d_in[6];
    const float* gg   = (const float*)d_in[7];
    const float* gb   = (const float*)d_in[8];
    const float* w1   = (const float*)d_in[9];
    const float* b1   = (const float*)d_in[10];
    const float* w2   = (const float*)d_in[11];
    const float* b2   = (const float*)d_in[12];
    const float* ow   = (const float*)d_in[13];
    const float* ob   = (const float*)d_in[14];
    const float* uw   = (const float*)d_in[15];
    const float* ub   = (const float*)d_in[16];
    const float* mw   = (const float*)d_in[17];
    const float* mb   = (const float*)d_in[18];
    const float* ew   = (const float*)d_in[19];
    const float* ebb  = (const float*)d_in[20];
    const float* fw   = (const float*)d_in[21];
    const float* fb   = (const float*)d_in[22];
    float* out = (float*)d_out;

    k_patchify<<<21504, 256>>>(x);
    k_conv3x3<448, 0><<<dim3(96, 4), 256>>>(pw, pb, pos);
    k_gnstats<<<64, 256>>>();
    k_xq<<<2048, 256>>>(gg, gb, w2);
    k_qgemm<<<dim3(64, 4), 256>>>(w1, b1, w2, b2);
    k_attn<<<16384, 128>>>(kc, vc);
    k_outproj<<<dim3(32, 4), 256>>>(ow, ob);
    k_conv3x3<128, 1><<<dim3(32, 14), 256>>>(uw, ub, (const float*)0);
    k_mod<<<1, 64>>>(emb, mw, mb);
    k_lnpart<<<128, 256>>>();
    k_lnfin<<<1, 32>>>();
    k_final<<<1024, 256>>>(ew, ebb, fw, fb, out);
}

// round 5
// speedup vs baseline: 1.1276x; 1.1276x over previous
#include <cuda_runtime.h>
#include <math.h>

// ---------------- problem constants ----------------
// B=4 S=3 E=7 IMG=256 PH=8 H=32 D=128 NH=4 DK=64 DC=128 DH=32 TEMB=256 LK=128 GROUPS=16
#define EPSV 1e-5f

// ---------------- scratch buffers (device globals; no allocation) ----------------
__device__ float g_xin [12 * 448 * 1024];   // patchified input (12,448,32,32)
__device__ float g_xg  [4 * 393216];        // conv1 out in xg flat layout (B, 393216)
__device__ float g_gn_mu[64];
__device__ float g_gn_rs[64];
__device__ float g_xq  [4096 * 128];        // S-collapsed normalized features
__device__ float g_q   [4096 * 256];        // query projections
__device__ float g_oflat[4096 * 128];       // attention output, (Nq, DC) flat
__device__ float g_o2  [4 * 128 * 1024];    // outproj output as (4,128,32,32)
__device__ float g_u   [4 * 7 * 65536];     // unpatched image (B,E,256,256) == skip
__device__ float g_mod [4 * 14];
__device__ float g_lnp [4 * 32 * 2];
__device__ float g_ln  [4 * 2];             // per-batch mu, rstd

// ---------------- K1: patchify (smem transpose, both sides coalesced) ----------------
// xin[img][ic][y][xx] = x[img][e][Y][X], Y=y*8+ph1, X=xx*8+ph2, ic=ph1*56+ph2*7+e
__global__ void __launch_bounds__(256) k_patchify(const float* __restrict__ x) {
    __shared__ float s[1024];
    int blk    = blockIdx.x;        // 12*7*64
    int rowblk = blk & 63;          // group of 4 input rows
    int ime    = blk >> 6;          // img*7 + e
    int img = ime / 7, e = ime % 7;
    int t = threadIdx.x;
    const float* src = x + ((size_t)ime * 256 + rowblk * 4) * 256;
    s[t]       = src[t];
    s[t + 256] = src[t + 256];
    s[t + 512] = src[t + 512];
    s[t + 768] = src[t + 768];
    __syncthreads();
    int ph2 = t >> 5, xx = t & 31;
#pragma unroll
    for (int r = 0; r < 4; ++r) {
        int Y = rowblk * 4 + r;
        int ph1 = Y & 7, y = Y >> 3;
        int ic = ph1 * 56 + ph2 * 7 + e;
        g_xin[((img * 448 + ic) << 10) + (y << 5) + xx] = s[r * 256 + xx * 8 + ph2];
    }
}

// ---------------- K2: 3x3 conv, implicit GEMM ----------------
// Tile: 128 px (4 rows x 32 cols) x 32 oc, 128 threads, 8px x 4oc per thread.
// All inner-loop SMEM traffic is LDS.128 (padded strides for alignment).
// MODE 0: in=g_xin (IC=448), out=g_xg scrambled layout, adds patch_b + pos_embed
// MODE 1: in=g_o2 (IC=128), out=g_u unpatch layout, adds unpatch_b
template<int IC, int MODE>
__global__ void __launch_bounds__(128) k_conv3x3(const float* __restrict__ w,
                                                 const float* __restrict__ bias,
                                                 const float* __restrict__ pos) {
    const int CK = 8;
    __shared__ float s_in[CK * 6 * 40];     // rows y0-1..y0+4, stored col = xg+1, pad to 40
    __shared__ float s_w [CK * 9 * 36];     // [rk=c*9+tap][oc_local], row padded to 36

    const float* in = (MODE == 0) ? g_xin : g_o2;

    int bx  = blockIdx.x;
    int img = bx >> 3, rb = bx & 7;
    int oc0 = blockIdx.y * 32;
    int t   = threadIdx.x;
    int tx  = t & 15, ty = t >> 4;   // 16 px-groups x 8 oc-groups
    int yl  = tx >> 2;               // 0..3 local out row
    int x0  = (tx & 3) * 8;          // 0,8,16,24 local out col base
    int ocl = ty * 4;                // 4 consecutive oc per thread
    int y0  = rb * 4;

    float acc[4][8];
#pragma unroll
    for (int j = 0; j < 4; ++j)
#pragma unroll
        for (int i = 0; i < 8; ++i) acc[j][i] = 0.f;

    for (int ch = 0; ch < IC / CK; ++ch) {
        int ic0 = ch * CK;
        __syncthreads();
        // stage input tile (halo, zero padded); stored index cx = xg + 1
        for (int idx = t; idx < CK * 6 * 40; idx += 128) {
            int c  = idx / 240;
            int rr = idx % 240;
            int ry = rr / 40, cx = rr % 40;
            int y  = y0 - 1 + ry;
            float v = 0.f;
            if (cx >= 1 && cx < 33 && y >= 0 && y < 32)
                v = in[((img * IC + ic0 + c) * 32 + y) * 32 + (cx - 1)];
            s_in[idx] = v;
        }
        // stage weights: coalesced over rk (contiguous in gmem)
        for (int idx = t; idx < 32 * CK * 9; idx += 128) {
            int o  = idx / 72;
            int rk = idx - o * 72;
            s_w[rk * 36 + o] = w[(oc0 + o) * (IC * 9) + ic0 * 9 + rk];
        }
        __syncthreads();

#pragma unroll 2
        for (int c = 0; c < CK; ++c) {
#pragma unroll
            for (int ky = 0; ky < 3; ++ky) {
                const float* rp = &s_in[(c * 6 + yl + ky) * 40 + x0];
                float4 r0 = *(const float4*)(rp);
                float4 r1 = *(const float4*)(rp + 4);
                float4 r2 = *(const float4*)(rp + 8);
                float rin[12] = {r0.x, r0.y, r0.z, r0.w,
                                 r1.x, r1.y, r1.z, r1.w,
                                 r2.x, r2.y, r2.z, r2.w};
#pragma unroll
                for (int kx = 0; kx < 3; ++kx) {
                    float4 wv = *(const float4*)&s_w[(c * 9 + ky * 3 + kx) * 36 + ocl];
                    float wj[4] = {wv.x, wv.y, wv.z, wv.w};
#pragma unroll
                    for (int j = 0; j < 4; ++j)
#pragma unroll
                        for (int i = 0; i < 8; ++i)
                            acc[j][i] = fmaf(wj[j], rin[kx + i], acc[j][i]);
                }
            }
        }
    }

    // epilogue
#pragma unroll
    for (int j = 0; j < 4; ++j) {
        int oc = oc0 + ocl + j;
        float bv = bias[oc];
        int y = y0 + yl;
        if (MODE == 0) {
            int b = img / 3, s = img % 3;
#pragma unroll
            for (int i = 0; i < 8; ++i) {
                int p = y * 32 + x0 + i;
                g_xg[b * 393216 + s * 131072 + oc * 1024 + p] =
                    acc[j][i] + bv + pos[oc * 1024 + p];
            }
        } else {
            int ph1 = oc / 56, r = oc % 56, ph2 = r / 7, e = r % 7;
#pragma unroll
            for (int i = 0; i < 8; ++i) {
                int xg = x0 + i;
                g_u[((img * 7 + e) * 256 + y * 8 + ph1) * 256 + (xg * 8 + ph2)] =
                    acc[j][i] + bv;
            }
        }
    }
}

// ---------------- K3: GroupNorm stats (64 contiguous groups of 24576) ----------------
__global__ void k_gnstats() {
    int bg = blockIdx.x;
    const float* p = g_xg + bg * 24576;
    int t = threadIdx.x;
    float s = 0.f, s2 = 0.f;
    for (int i = t; i < 24576; i += 256) { float v = p[i]; s += v; s2 += v * v; }
    __shared__ float rs[256], rq[256];
    rs[t] = s; rq[t] = s2; __syncthreads();
    for (int off = 128; off > 0; off >>= 1) {
        if (t < off) { rs[t] += rs[t + off]; rq[t] += rq[t + off]; }
        __syncthreads();
    }
    if (t == 0) {
        float mu = rs[0] * (1.f / 24576.f);
        float var = rq[0] * (1.f / 24576.f) - mu * mu;
        g_gn_mu[bg] = mu;
        g_gn_rs[bg] = rsqrtf(var + EPSV);
    }
}

// ---------------- K4: S-collapse with GN applied ----------------
__global__ void k_xq(const float* __restrict__ gamma, const float* __restrict__ beta,
                     const float* __restrict__ w2) {
    int idx = blockIdx.x * 256 + threadIdx.x;
    if (idx >= 4096 * 128) return;
    int nq = idx >> 7, dq = idx & 127;
    int b = nq >> 10;
    int fbase = (nq & 1023) * 384 + dq * 3;
    const float* xb = g_xg + b * 393216;
    float accv = 0.f;
#pragma unroll
    for (int sq = 0; sq < 3; ++sq) {
        int f  = fbase + sq;
        int dp = f / 3072;                 // channel for gamma/beta
        int gi = b * 16 + f / 24576;       // group
        float v = xb[f];
        float xn = (v - g_gn_mu[gi]) * g_gn_rs[gi] * gamma[dp] + beta[dp];
        accv = fmaf(w2[sq], xn, accv);
    }
    g_xq[idx] = accv;
}

// ---------------- K5: q GEMM (4096x128 @ 128x256) ----------------
__global__ void __launch_bounds__(256) k_qgemm(const float* __restrict__ w1,
                                               const float* __restrict__ b1,
                                               const float* __restrict__ w2,
                                               const float* __restrict__ b2p) {
    __shared__ float As[64 * 68];
    __shared__ float Bs[64 * 68];
    int r0 = blockIdx.x * 64, o0 = blockIdx.y * 64;
    int t = threadIdx.x;
    int cth = (t & 15) * 4, rth = (t >> 4) * 4;
    float acc[4][4];
#pragma unroll
    for (int a = 0; a < 4; ++a)
#pragma unroll
        for (int c = 0; c < 4; ++c) acc[a][c] = 0.f;

    for (int k0 = 0; k0 < 128; k0 += 64) {
        __syncthreads();
        for (int idx = t; idx < 4096; idx += 256) {
            int jj = idx & 63, rr = idx >> 6;
            As[jj * 68 + rr] = g_xq[(r0 + rr) * 128 + k0 + jj];
            Bs[jj * 68 + rr] = w1[(o0 + rr) * 128 + k0 + jj];
        }
        __syncthreads();
#pragma unroll 8
        for (int j = 0; j < 64; ++j) {
            float4 av = *(const float4*)&As[j * 68 + rth];
            float4 bv = *(const float4*)&Bs[j * 68 + cth];
            float a[4] = {av.x, av.y, av.z, av.w};
            float bb[4] = {bv.x, bv.y, bv.z, bv.w};
#pragma unroll
            for (int r = 0; r < 4; ++r)
#pragma unroll
                for (int c = 0; c < 4; ++c) acc[r][c] = fmaf(a[r], bb[c], acc[r][c]);
        }
    }
    float w2s = w2[0] + w2[1] + w2[2];
    float b2v = b2p[0];
#pragma unroll
    for (int r = 0; r < 4; ++r)
#pragma unroll
        for (int c = 0; c < 4; ++c) {
            int o = o0 + cth + c;
            g_q[(r0 + rth + r) * 256 + o] = acc[r][c] + b1[o] * w2s + b2v;
        }
}

// ---------------- K6: per-row attention (16384 rows) ----------------
__global__ void __launch_bounds__(128) k_attn(const float* __restrict__ kc,
                                              const float* __restrict__ vc) {
    int n = blockIdx.x;
    int t = threadIdx.x;
    int lane = t & 31, wid = t >> 5;
    __shared__ float attn_s[128];
    __shared__ float red[128];

    const float* qp = g_q + (size_t)(n >> 2) * 256 + (n & 3) * 64;
    float2 q2 = *(const float2*)(qp + 2 * lane);
    const float* kb = kc + (size_t)n * 8192;

#pragma unroll 4
    for (int i = 0; i < 32; ++i) {
        int l = wid * 32 + i;
        float2 kv = *(const float2*)(kb + l * 64 + 2 * lane);
        float p = q2.x * kv.x + q2.y * kv.y;
        p += __shfl_xor_sync(0xffffffffu, p, 16);
        p += __shfl_xor_sync(0xffffffffu, p, 8);
        p += __shfl_xor_sync(0xffffffffu, p, 4);
        p += __shfl_xor_sync(0xffffffffu, p, 2);
        p += __shfl_xor_sync(0xffffffffu, p, 1);
        if (lane == i) attn_s[l] = p * 0.125f;   // 1/sqrt(64)
    }
    __syncthreads();

    float v = attn_s[t];
    float m = v;
    m = fmaxf(m, __shfl_xor_sync(0xffffffffu, m, 16));
    m = fmaxf(m, __shfl_xor_sync(0xffffffffu, m, 8));
    m = fmaxf(m, __shfl_xor_sync(0xffffffffu, m, 4));
    m = fmaxf(m, __shfl_xor_sync(0xffffffffu, m, 2));
    m = fmaxf(m, __shfl_xor_sync(0xffffffffu, m, 1));
    if (lane == 0) red[wid] = m;
    __syncthreads();
    float bm = fmaxf(fmaxf(red[0], red[1]), fmaxf(red[2], red[3]));
    float e = expf(v - bm);
    float s = e;
    s += __shfl_xor_sync(0xffffffffu, s, 16);
    s += __shfl_xor_sync(0xffffffffu, s, 8);
    s += __shfl_xor_sync(0xffffffffu, s, 4);
    s += __shfl_xor_sync(0xffffffffu, s, 2);
    s += __shfl_xor_sync(0xffffffffu, s, 1);
    __syncthreads();
    if (lane == 0) red[wid] = s;
    __syncthreads();
    float bs = red[0] + red[1] + red[2] + red[3];
    attn_s[t] = e * (1.f / bs);
    __syncthreads();

    int c = t & 31, chunk = t >> 5;
    const float* vb = vc + (size_t)n * 4096;
    float acc = 0.f;
#pragma unroll 8
    for (int i = 0; i < 32; ++i) {
        int l = chunk * 32 + i;
        acc = fmaf(attn_s[l], vb[l * 32 + c], acc);
    }
    __syncthreads();
    red[t] = acc;
    __syncthreads();
    if (t < 32) {
        float o = red[t] + red[32 + t] + red[64 + t] + red[96 + t];
        // o.reshape(NH,Nq,DH).transpose(1,0,2): row n -> (h=n/4096, nq=n%4096)
        g_oflat[(n & 4095) * 128 + (n >> 12) * 32 + t] = o;
    }
}

// ---------------- K7: outproj 128x128 per-pixel matvec ----------------
__global__ void __launch_bounds__(256) k_outproj(const float* __restrict__ w,
                                                 const float* __restrict__ bias) {
    __shared__ float in_s[32 * 128];
    __shared__ float w_s[32 * 36];
    int b = blockIdx.x >> 3, pt = blockIdx.x & 7;
    int oc0 = blockIdx.y * 32;
    int t = threadIdx.x;
    int tx = t & 15, ty = t >> 4;
    int p0 = tx * 8, ol = ty * 2;
    float acc[2][8];
#pragma unroll
    for (int j = 0; j < 2; ++j)
#pragma unroll
        for (int i = 0; i < 8; ++i) acc[j][i] = 0.f;

    for (int c0 = 0; c0 < 128; c0 += 32) {
        __syncthreads();
        for (int idx = t; idx < 32 * 128; idx += 256) {
            int c = idx >> 7, p = idx & 127;
            in_s[idx] = g_oflat[b * 131072 + (c0 + c) * 1024 + pt * 128 + p];
        }
        for (int idx = t; idx < 32 * 32; idx += 256) {
            int c = idx & 31, o = idx >> 5;
            w_s[c * 36 + o] = w[(oc0 + o) * 128 + c0 + c];
        }
        __syncthreads();
#pragma unroll 4
        for (int c = 0; c < 32; ++c) {
            float w0 = w_s[c * 36 + ol], w1 = w_s[c * 36 + ol + 1];
            float4 i0 = *(const float4*)&in_s[c * 128 + p0];
            float4 i1 = *(const float4*)&in_s[c * 128 + p0 + 4];
            float iv[8] = {i0.x, i0.y, i0.z, i0.w, i1.x, i1.y, i1.z, i1.w};
#pragma unroll
            for (int i = 0; i < 8; ++i) {
                acc[0][i] = fmaf(w0, iv[i], acc[0][i]);
                acc[1][i] = fmaf(w1, iv[i], acc[1][i]);
            }
        }
    }
#pragma unroll
    for (int j = 0; j < 2; ++j) {
        int oc = oc0 + ol + j;
        float bv = bias[oc];
#pragma unroll
        for (int i = 0; i < 8; ++i)
            g_o2[(b * 128 + oc) * 1024 + pt * 128 + p0 + i] = acc[j][i] + bv;
    }
}

// ---------------- K9: modulation c = silu(emb) @ mod_w.T + mod_b ----------------
__global__ void k_mod(const float* __restrict__ emb, const float* __restrict__ mw,
                      const float* __restrict__ mb) {
    int t = threadIdx.x;
    if (t < 56) {
        int b = t / 14, o = t % 14;
        float accv = mb[o];
        for (int k = 0; k < 256; ++k) {
            float e = emb[b * 256 + k];
            float si = e / (1.f + expf(-e));
            accv = fmaf(si, mw[o * 256 + k], accv);
        }
        g_mod[t] = accv;
    }
}

// ---------------- K10/K11: LayerNorm over u per batch ----------------
__global__ void k_lnpart() {
    int bidx = blockIdx.x;
    int b = bidx >> 5, part = bidx & 31;
    const float* p = g_u + b * 458752 + part * 14336;
    int t = threadIdx.x;
    float s = 0.f, s2 = 0.f;
    for (int i = t; i < 14336; i += 256) { float v = p[i]; s += v; s2 += v * v; }
    __shared__ float rs[256], rq[256];
    rs[t] = s; rq[t] = s2; __syncthreads();
    for (int off = 128; off > 0; off >>= 1) {
        if (t < off) { rs[t] += rs[t + off]; rq[t] += rq[t + off]; }
        __syncthreads();
    }
    if (t == 0) { g_lnp[bidx * 2] = rs[0]; g_lnp[bidx * 2 + 1] = rq[0]; }
}

__global__ void k_lnfin() {
    int t = threadIdx.x;
    if (t < 4) {
        float s = 0.f, s2 = 0.f;
        for (int i = 0; i < 32; ++i) {
            s  += g_lnp[(t * 32 + i) * 2];
            s2 += g_lnp[(t * 32 + i) * 2 + 1];
        }
        float mu = s * (1.f / 458752.f);
        float var = s2 * (1.f / 458752.f) - mu * mu;
        g_ln[t * 2] = mu;
        g_ln[t * 2 + 1] = rsqrtf(var + EPSV);
    }
}

// ---------------- K12: final elementwise tail ----------------
__device__ __forceinline__ float gelu_exact(float x) {
    return 0.5f * x * (1.f + erff(x * 0.70710678118654752f));
}

__global__ void k_final(const float* __restrict__ ew, const float* __restrict__ eb,
                        const float* __restrict__ fw, const float* __restrict__ fb,
                        float* __restrict__ out) {
    int gid = blockIdx.x * 256 + threadIdx.x;
    if (gid >= 262144) return;
    int b = gid >> 16, p = gid & 65535;
    float mu = g_ln[b * 2], rsd = g_ln[b * 2 + 1];
    float uv[7], un[7];
#pragma unroll
    for (int e = 0; e < 7; ++e) {
        uv[e] = g_u[b * 458752 + e * 65536 + p];
        float sc = g_mod[b * 14 + e];
        float sh = g_mod[b * 14 + 7 + e];
        un[e] = (uv[e] - mu) * rsd * (1.f + sc) + sh;
    }
    float en[14];
#pragma unroll
    for (int o = 0; o < 14; ++o) {
        float a = eb[o];
#pragma unroll
        for (int e = 0; e < 7; ++e) a = fmaf(ew[o * 7 + e], un[e], a);
        en[o] = a;
    }
    float hf[7];
#pragma unroll
    for (int e = 0; e < 7; ++e)
        hf[e] = gelu_exact(un[e]) + en[e] * gelu_exact(en[7 + e]);
#pragma unroll
    for (int o = 0; o < 7; ++o) {
        float a = fb[o];
#pragma unroll
        for (int e = 0; e < 7; ++e) a = fmaf(fw[o * 7 + e], hf[e], a);
        out[b * 458752 + o * 65536 + p] = a + uv[o];
    }
}

// ---------------- launch ----------------
extern "C" void kernel_launch(void* const* d_in, const int* in_sizes, int n_in,
                              void* d_out, int out_size) {
    const float* x    = (const float*)d_in[0];
    const float* kc   = (const float*)d_in[1];
    const float* vc   = (const float*)d_in[2];
    const float* emb  = (const float*)d_in[3];
    const float* pos  = (const float*)d_in[4];
    const float* pw   = (const float*)d_in[5];
    const float* pb   = (const float*)d_in[6];
    const float* gg   = (const float*)d_in[7];
    const float* gb   = (const float*)d_in[8];
    const float* w1   = (const float*)d_in[9];
    const float* b1   = (const float*)d_in[10];
    const float* w2   = (const float*)d_in[11];
    const float* b2   = (const float*)d_in[12];
    const float* ow   = (const float*)d_in[13];
    const float* ob   = (const float*)d_in[14];
    const float* uw   = (const float*)d_in[15];
    const float* ub   = (const float*)d_in[16];
    const float* mw   = (const float*)d_in[17];
    const float* mb   = (const float*)d_in[18];
    const float* ew   = (const float*)d_in[19];
    const float* ebb  = (const float*)d_in[20];
    const float* fw   = (const float*)d_in[21];
    const float* fb   = (const float*)d_in[22];
    float* out = (float*)d_out;

    k_patchify<<<5376, 256>>>(x);
    k_conv3x3<448, 0><<<dim3(96, 4), 128>>>(pw, pb, pos);
    k_gnstats<<<64, 256>>>();
    k_xq<<<2048, 256>>>(gg, gb, w2);
    k_qgemm<<<dim3(64, 4), 256>>>(w1, b1, w2, b2);
    k_attn<<<16384, 128>>>(kc, vc);
    k_outproj<<<dim3(32, 4), 256>>>(ow, ob);
    k_conv3x3<128, 1><<<dim3(32, 14), 128>>>(uw, ub, (const float*)0);
    k_mod<<<1, 64>>>(emb, mw, mb);
    k_lnpart<<<128, 256>>>();
    k_lnfin<<<1, 32>>>();
    k_final<<<1024, 256>>>(ew, ebb, fw, fb, out);
}